// round 17
// baseline (speedup 1.0000x reference)
#include <cuda_runtime.h>
#include <cuda_bf16.h>
#include <cstdint>

typedef unsigned long long ull;
typedef uint32_t u32;

// ---------------- fragment arena byte offsets (256 B per 16x8 B-fragment) ----------------
static constexpr u32 TA_H = 0;      // towerA: Kp=48,Np=72 -> 27 frags
static constexpr u32 TA_L = 6912;
static constexpr u32 TB_H = 13824;  // towerB: Kp=112,Np=72 -> 63
static constexpr u32 TB_L = 29952;
static constexpr u32 L0_H = 46080;  // L0: Kp=144,Np=40 -> 45
static constexpr u32 L0_L = 58880;
static constexpr u32 L1_H = 71680;  // L1: Kp=48,Np=40 -> 15
static constexpr u32 L1_L = 75520;
static constexpr u32 L2_H = 79360;  // L2: Kp=48,Np=24 -> 9
static constexpr u32 L2_L = 81664;
static constexpr u32 L3_H = 83968;  // L3-6: Kp=32,Np=24 -> 6
static constexpr u32 L3_L = 85504;
static constexpr u32 L4_H = 87040;
static constexpr u32 L4_L = 88576;
static constexpr u32 L5_H = 90112;
static constexpr u32 L5_L = 91648;
static constexpr u32 L6_H = 93184;
static constexpr u32 L6_L = 94720;
static constexpr u32 L7_H = 96256;  // L7: Kp=32,Np=8 -> 2
static constexpr u32 L7_L = 96768;
static constexpr u32 BIAS_B = 97280;       // float arena
static constexpr u32 SMEM_TOTAL = 98816;   // 96.5 KB; 1 CTA/SM

static constexpr int JTA = 0, JTB = 72, J0 = 144, J1 = 184, J2 = 224, J3 = 248;
static constexpr int J4 = 272, J5 = 296, J6 = 320, J7 = 344;
static constexpr int JW8 = 352, JB8 = 368, JW9 = 370, JB9 = 372;  // W8 padded 8x2

__device__ int g_ctr;
__global__ void reset_ctr_kernel() { g_ctr = 0; }

__device__ __forceinline__ float lrelu(float x) { return fmaxf(x, 0.01f * x); }

__device__ __forceinline__ u32 cvtpack(float v0, float v1) {
    u32 r; asm("cvt.rn.bf16x2.f32 %0, %1, %2;" : "=r"(r) : "f"(v1), "f"(v0)); return r;
}
__device__ __forceinline__ void split_pack(float v0, float v1, u32& h, u32& l) {
    h = cvtpack(v0, v1);
    float h0 = __uint_as_float(h << 16);
    float h1 = __uint_as_float(h & 0xFFFF0000u);
    l = cvtpack(v0 - h0, v1 - h1);
}

__device__ __forceinline__ void mma16816(float& c0, float& c1, float& c2, float& c3,
                                         u32 a0, u32 a1, u32 a2, u32 a3, u32 b0, u32 b1) {
    asm volatile(
        "mma.sync.aligned.m16n8k16.row.col.f32.bf16.bf16.f32 "
        "{%0,%1,%2,%3}, {%4,%5,%6,%7}, {%8,%9}, {%0,%1,%2,%3};"
        : "+f"(c0), "+f"(c1), "+f"(c2), "+f"(c3)
        : "r"(a0), "r"(a1), "r"(a2), "r"(a3), "r"(b0), "r"(b1));
}
__device__ __forceinline__ void mma_acc(float* c, const u32* A, u32 b0, u32 b1) {
    mma16816(c[0], c[1], c[2], c[3], A[0], A[1], A[2], A[3], b0, b1);
}

// D quad -> A slot s in per-tile fragment arrays (stride 12 per tile not needed here)
__device__ __forceinline__ void toslot(float d0, float d1, float d2, float d3,
                                       u32* h, u32* l, int s, bool act) {
    if (act) { d0 = lrelu(d0); d1 = lrelu(d1); d2 = lrelu(d2); d3 = lrelu(d3); }
    split_pack(d0, d1, h[2 * s + 0], l[2 * s + 0]);
    split_pack(d2, d3, h[2 * s + 1], l[2 * s + 1]);
}

// bounds-checked split loads
__device__ __forceinline__ void ld_split(const float* __restrict__ p, int c, int Kreal,
                                         u32& h, u32& l) {
    float v0 = (c < Kreal) ? __ldg(p + c) : 0.0f;
    float v1 = (c + 1 < Kreal) ? __ldg(p + c + 1) : 0.0f;
    split_pack(v0, v1, h, l);
}
__device__ __forceinline__ void ld_split2(const float* __restrict__ p, int c, int Kreal,
                                          u32& h, u32& l) {
    float v0 = 0.0f, v1 = 0.0f;
    if (c + 1 < Kreal) {
        float2 v = __ldg(reinterpret_cast<const float2*>(p + c));
        v0 = v.x; v1 = v.y;
    }
    split_pack(v0, v1, h, l);
}
template <int VEC>
__device__ __forceinline__ void ld_frag(const float* p0, const float* p1, int c, int Kreal,
                                        u32* fh, u32* fl) {
    if (VEC) {
        ld_split2(p0, c, Kreal, fh[0], fl[0]);
        ld_split2(p1, c, Kreal, fh[1], fl[1]);
        ld_split2(p0, c + 8, Kreal, fh[2], fl[2]);
        ld_split2(p1, c + 8, Kreal, fh[3], fl[3]);
    } else {
        ld_split(p0, c, Kreal, fh[0], fl[0]);
        ld_split(p1, c, Kreal, fh[1], fl[1]);
        ld_split(p0, c + 8, Kreal, fh[2], fl[2]);
        ld_split(p1, c + 8, Kreal, fh[3], fl[3]);
    }
}

// Two-tile tower half: columns [NB0, NB0+NBC) of a 72-wide tower (NBT=9 frag stride).
// Weights loaded once per (kb,nb), reused for both tiles. D layout: D[t*4*NBC + 4*nb + j].
template <int KB, int VEC, int NB0, int NBC>
__device__ void tower_half2(const float* __restrict__ pa0, const float* __restrict__ pa1,
                            const float* __restrict__ pb0, const float* __restrict__ pb1,
                            int Kreal, const char* smc, u32 offH, u32 offL, int bidx,
                            int lane, float* D) {
    const int t2 = (lane & 3) << 1;
    const float* biasp = reinterpret_cast<const float*>(smc + BIAS_B) + bidx;
    float acc[8 * NBC];
#pragma unroll
    for (int nb = 0; nb < NBC; nb++) {
        float2 bv = *reinterpret_cast<const float2*>(biasp + (NB0 + nb) * 8 + t2);
        acc[4 * nb + 0] = bv.x; acc[4 * nb + 1] = bv.y;
        acc[4 * nb + 2] = bv.x; acc[4 * nb + 3] = bv.y;
        acc[4 * NBC + 4 * nb + 0] = bv.x; acc[4 * NBC + 4 * nb + 1] = bv.y;
        acc[4 * NBC + 4 * nb + 2] = bv.x; acc[4 * NBC + 4 * nb + 3] = bv.y;
    }
    const char* ph = smc + offH + (lane << 3);
    const char* pl = smc + offL + (lane << 3);
    u32 cfh[8], cfl[8], nfh[8], nfl[8];
    ld_frag<VEC>(pa0, pa1, t2, Kreal, cfh + 0, cfl + 0);
    ld_frag<VEC>(pb0, pb1, t2, Kreal, cfh + 4, cfl + 4);
#pragma unroll
    for (int kb = 0; kb < KB; kb++) {
        if (kb + 1 < KB) {
            ld_frag<VEC>(pa0, pa1, (kb + 1) * 16 + t2, Kreal, nfh + 0, nfl + 0);
            ld_frag<VEC>(pb0, pb1, (kb + 1) * 16 + t2, Kreal, nfh + 4, nfl + 4);
        }
        u32 b0[NBC], b1[NBC];
#pragma unroll
        for (int nb = 0; nb < NBC; nb++) {
            ull w = *reinterpret_cast<const ull*>(ph + (kb * 9 + NB0 + nb) * 256);
            b0[nb] = (u32)w; b1[nb] = (u32)(w >> 32);
            mma_acc(acc + 4 * nb, cfh + 0, b0[nb], b1[nb]);
            mma_acc(acc + 4 * NBC + 4 * nb, cfh + 4, b0[nb], b1[nb]);
        }
#pragma unroll
        for (int nb = 0; nb < NBC; nb++) {
            mma_acc(acc + 4 * nb, cfl + 0, b0[nb], b1[nb]);
            mma_acc(acc + 4 * NBC + 4 * nb, cfl + 4, b0[nb], b1[nb]);
        }
#pragma unroll
        for (int nb = 0; nb < NBC; nb++) {
            ull w = *reinterpret_cast<const ull*>(pl + (kb * 9 + NB0 + nb) * 256);
            mma_acc(acc + 4 * nb, cfh + 0, (u32)w, (u32)(w >> 32));
            mma_acc(acc + 4 * NBC + 4 * nb, cfh + 4, (u32)w, (u32)(w >> 32));
        }
#pragma unroll
        for (int i = 0; i < 8; i++) { cfh[i] = nfh[i]; cfl[i] = nfl[i]; }
    }
#pragma unroll
    for (int i = 0; i < 8 * NBC; i++) D[i] = acc[i];
}

// One L0 k-block for BOTH tiles; sh/sl layout: tile t at [t*4 .. t*4+3].
__device__ __forceinline__ void l0_kb2(float* acc /*[40], t stride 20*/, const u32* sh,
                                       const u32* sl, int kb, const char* smc, int lane) {
    const char* ph = smc + L0_H + (lane << 3);
    const char* pl = smc + L0_L + (lane << 3);
    u32 b0[5], b1[5];
#pragma unroll
    for (int nb = 0; nb < 5; nb++) {
        ull w = *reinterpret_cast<const ull*>(ph + (kb * 5 + nb) * 256);
        b0[nb] = (u32)w; b1[nb] = (u32)(w >> 32);
        mma_acc(acc + 4 * nb, sh + 0, b0[nb], b1[nb]);
        mma_acc(acc + 20 + 4 * nb, sh + 4, b0[nb], b1[nb]);
    }
#pragma unroll
    for (int nb = 0; nb < 5; nb++) {
        mma_acc(acc + 4 * nb, sl + 0, b0[nb], b1[nb]);
        mma_acc(acc + 20 + 4 * nb, sl + 4, b0[nb], b1[nb]);
    }
#pragma unroll
    for (int nb = 0; nb < 5; nb++) {
        ull w = *reinterpret_cast<const ull*>(pl + (kb * 5 + nb) * 256);
        mma_acc(acc + 4 * nb, sh + 0, (u32)w, (u32)(w >> 32));
        mma_acc(acc + 20 + 4 * nb, sh + 4, (u32)w, (u32)(w >> 32));
    }
}

// Two-tile dense layer; A frags per tile at stride 12 (h1[24]); D[t*4*NB + ...].
template <int KB, int NB>
__device__ __forceinline__ void layer2(const u32* Ah, const u32* Al, const char* smc,
                                       u32 offH, u32 offL, int bidx, int lane, float* D) {
    const int t2 = (lane & 3) << 1;
    const float* biasp = reinterpret_cast<const float*>(smc + BIAS_B) + bidx;
    float acc[8 * NB];
#pragma unroll
    for (int nb = 0; nb < NB; nb++) {
        float2 bv = *reinterpret_cast<const float2*>(biasp + nb * 8 + t2);
        acc[4 * nb + 0] = bv.x; acc[4 * nb + 1] = bv.y;
        acc[4 * nb + 2] = bv.x; acc[4 * nb + 3] = bv.y;
        acc[4 * NB + 4 * nb + 0] = bv.x; acc[4 * NB + 4 * nb + 1] = bv.y;
        acc[4 * NB + 4 * nb + 2] = bv.x; acc[4 * NB + 4 * nb + 3] = bv.y;
    }
    const char* ph = smc + offH + (lane << 3);
    const char* pl = smc + offL + (lane << 3);
#pragma unroll
    for (int kb = 0; kb < KB; kb++) {
        u32 b0[NB], b1[NB];
#pragma unroll
        for (int nb = 0; nb < NB; nb++) {
            ull w = *reinterpret_cast<const ull*>(ph + (kb * NB + nb) * 256);
            b0[nb] = (u32)w; b1[nb] = (u32)(w >> 32);
            mma_acc(acc + 4 * nb, Ah + 4 * kb, b0[nb], b1[nb]);
            mma_acc(acc + 4 * NB + 4 * nb, Ah + 12 + 4 * kb, b0[nb], b1[nb]);
        }
#pragma unroll
        for (int nb = 0; nb < NB; nb++) {
            mma_acc(acc + 4 * nb, Al + 4 * kb, b0[nb], b1[nb]);
            mma_acc(acc + 4 * NB + 4 * nb, Al + 12 + 4 * kb, b0[nb], b1[nb]);
        }
    }
#pragma unroll
    for (int kb = 0; kb < KB; kb++) {
#pragma unroll
        for (int nb = 0; nb < NB; nb++) {
            ull w = *reinterpret_cast<const ull*>(pl + (kb * NB + nb) * 256);
            mma_acc(acc + 4 * nb, Ah + 4 * kb, (u32)w, (u32)(w >> 32));
            mma_acc(acc + 4 * NB + 4 * nb, Ah + 12 + 4 * kb, (u32)w, (u32)(w >> 32));
        }
    }
#pragma unroll
    for (int i = 0; i < 8 * NB; i++) D[i] = acc[i];
}

// W [K,N] row-major fp32 -> hi/lo B fragments. mode 1 = L0 concat row remap (Kp=144).
__device__ void prepW(char* smc, const float* __restrict__ W, int K, int N, int NBfr,
                      u32 offH, u32 offL, int tid, int nt, int mode) {
    for (int i = tid; i < K * N; i += nt) {
        int k = i / N, n = i - k * N;
        int kp = k;
        if (mode == 1) kp = (k < 68) ? k : k + 4;
        u32 fo = (u32)(((kp >> 4) * NBfr + (n >> 3)) << 8)
               + (u32)((((n & 7) << 2) | ((kp & 7) >> 1)) << 3)
               + (u32)(((kp >> 3) & 1) << 2)
               + (u32)((kp & 1) << 1);
        float v = W[i];
        __nv_bfloat16 h = __float2bfloat16(v);
        float lo = v - __bfloat162float(h);
        *reinterpret_cast<__nv_bfloat16*>(smc + offH + fo) = h;
        *reinterpret_cast<__nv_bfloat16*>(smc + offL + fo) = __float2bfloat16(lo);
    }
}

__global__ __launch_bounds__(384)
void Net_67954972557347_kernel(
    const float* __restrict__ a, const float* __restrict__ b, const float* __restrict__ meta,
    const float* __restrict__ Wa, const float* __restrict__ ba,
    const float* __restrict__ Wb, const float* __restrict__ bb,
    const float* __restrict__ W0, const float* __restrict__ B0,
    const float* __restrict__ W1, const float* __restrict__ B1,
    const float* __restrict__ W2, const float* __restrict__ B2,
    const float* __restrict__ W3, const float* __restrict__ B3,
    const float* __restrict__ W4, const float* __restrict__ B4,
    const float* __restrict__ W5, const float* __restrict__ B5,
    const float* __restrict__ W6, const float* __restrict__ B6,
    const float* __restrict__ W7, const float* __restrict__ B7,
    const float* __restrict__ W8, const float* __restrict__ B8,
    const float* __restrict__ W9, const float* __restrict__ B9,
    float* __restrict__ outp, int npairs)
{
    extern __shared__ char smc[];
    const int tid = threadIdx.x, nt = blockDim.x, lane = tid & 31;

    for (u32 o = (u32)tid * 16; o < SMEM_TOTAL; o += (u32)nt * 16)
        *reinterpret_cast<uint4*>(smc + o) = make_uint4(0, 0, 0, 0);
    __syncthreads();

    prepW(smc, Wa, 45, 68, 9, TA_H, TA_L, tid, nt, 0);
    prepW(smc, Wb, 102, 68, 9, TB_H, TB_L, tid, nt, 0);
    prepW(smc, W0, 140, 34, 5, L0_H, L0_L, tid, nt, 1);
    prepW(smc, W1, 34, 34, 5, L1_H, L1_L, tid, nt, 0);
    prepW(smc, W2, 34, 20, 3, L2_H, L2_L, tid, nt, 0);
    prepW(smc, W3, 20, 20, 3, L3_H, L3_L, tid, nt, 0);
    prepW(smc, W4, 20, 20, 3, L4_H, L4_L, tid, nt, 0);
    prepW(smc, W5, 20, 20, 3, L5_H, L5_L, tid, nt, 0);
    prepW(smc, W6, 20, 20, 3, L6_H, L6_L, tid, nt, 0);
    prepW(smc, W7, 20, 5, 1, L7_H, L7_L, tid, nt, 0);
    float* bs = reinterpret_cast<float*>(smc + BIAS_B);
    if (tid < 68) { bs[JTA + tid] = ba[tid]; bs[JTB + tid] = bb[tid]; }
    if (tid < 34) { bs[J0 + tid] = B0[tid]; bs[J1 + tid] = B1[tid]; }
    if (tid < 20) {
        bs[J2 + tid] = B2[tid]; bs[J3 + tid] = B3[tid]; bs[J4 + tid] = B4[tid];
        bs[J5 + tid] = B5[tid]; bs[J6 + tid] = B6[tid];
    }
    if (tid < 5)  bs[J7 + tid] = B7[tid];
    if (tid < 10) bs[JW8 + tid] = W8[tid];
    if (tid < 2)  { bs[JB8 + tid] = B8[tid]; bs[JW9 + tid] = W9[tid]; }
    if (tid == 0) bs[JB9] = B9[0];
    __syncthreads();

    const int t2 = (lane & 3) << 1;

    for (;;) {
        int pair;
        if (lane == 0) pair = atomicAdd(&g_ctr, 1);
        pair = __shfl_sync(0xFFFFFFFFu, pair, 0);
        if (pair >= npairs) break;

        const int base = pair * 32;
        const int rA0 = base + (lane >> 2), rA1 = rA0 + 8;        // tile 0
        const int rB0 = base + 16 + (lane >> 2), rB1 = rB0 + 8;   // tile 1

        float accL0[40];   // t0: 0..19, t1: 20..39
#pragma unroll
        for (int nb = 0; nb < 5; nb++) {
            float2 bv = *reinterpret_cast<const float2*>(bs + J0 + nb * 8 + t2);
            accL0[4 * nb + 0] = bv.x; accL0[4 * nb + 1] = bv.y;
            accL0[4 * nb + 2] = bv.x; accL0[4 * nb + 3] = bv.y;
            accL0[20 + 4 * nb + 0] = bv.x; accL0[20 + 4 * nb + 1] = bv.y;
            accL0[20 + 4 * nb + 2] = bv.x; accL0[20 + 4 * nb + 3] = bv.y;
        }
        u32 sh[8], sl[8];  // rolling slot pair per tile (t*4 + 2*half + {0,1})

        // ---- towerA half0: slots 0..4 ----
        {
            float D[40];
            tower_half2<3, 0, 0, 5>(a + (size_t)rA0 * 45, a + (size_t)rA1 * 45,
                                    a + (size_t)rB0 * 45, a + (size_t)rB1 * 45,
                                    45, smc, TA_H, TA_L, JTA, lane, D);
#pragma unroll
            for (int nb = 0; nb < 5; nb++) {
                const int s = nb, half = s & 1;
#pragma unroll
                for (int t = 0; t < 2; t++) {
                    float d0 = lrelu(D[t * 20 + 4 * nb + 0]), d1 = lrelu(D[t * 20 + 4 * nb + 1]);
                    float d2 = lrelu(D[t * 20 + 4 * nb + 2]), d3 = lrelu(D[t * 20 + 4 * nb + 3]);
                    split_pack(d0, d1, sh[t * 4 + 2 * half + 0], sl[t * 4 + 2 * half + 0]);
                    split_pack(d2, d3, sh[t * 4 + 2 * half + 1], sl[t * 4 + 2 * half + 1]);
                }
                if (half) l0_kb2(accL0, sh, sl, s >> 1, smc, lane);
            }
        }
        // ---- towerA half1: slots 5..8 ----
        {
            float D[32];
            tower_half2<3, 0, 5, 4>(a + (size_t)rA0 * 45, a + (size_t)rA1 * 45,
                                    a + (size_t)rB0 * 45, a + (size_t)rB1 * 45,
                                    45, smc, TA_H, TA_L, JTA, lane, D);
#pragma unroll
            for (int nb = 0; nb < 4; nb++) {
                const int s = 5 + nb, half = s & 1;
#pragma unroll
                for (int t = 0; t < 2; t++) {
                    float d0 = lrelu(D[t * 16 + 4 * nb + 0]), d1 = lrelu(D[t * 16 + 4 * nb + 1]);
                    float d2 = lrelu(D[t * 16 + 4 * nb + 2]), d3 = lrelu(D[t * 16 + 4 * nb + 3]);
                    split_pack(d0, d1, sh[t * 4 + 2 * half + 0], sl[t * 4 + 2 * half + 0]);
                    split_pack(d2, d3, sh[t * 4 + 2 * half + 1], sl[t * 4 + 2 * half + 1]);
                }
                if (half) l0_kb2(accL0, sh, sl, s >> 1, smc, lane);
            }
        }
        // ---- towerB half0: slots 9..13 ----
        {
            float D[40];
            tower_half2<7, 1, 0, 5>(b + (size_t)rA0 * 102, b + (size_t)rA1 * 102,
                                    b + (size_t)rB0 * 102, b + (size_t)rB1 * 102,
                                    102, smc, TB_H, TB_L, JTB, lane, D);
#pragma unroll
            for (int nb = 0; nb < 5; nb++) {
                const int s = 9 + nb, half = s & 1;
#pragma unroll
                for (int t = 0; t < 2; t++) {
                    float d0 = lrelu(D[t * 20 + 4 * nb + 0]), d1 = lrelu(D[t * 20 + 4 * nb + 1]);
                    float d2 = lrelu(D[t * 20 + 4 * nb + 2]), d3 = lrelu(D[t * 20 + 4 * nb + 3]);
                    split_pack(d0, d1, sh[t * 4 + 2 * half + 0], sl[t * 4 + 2 * half + 0]);
                    split_pack(d2, d3, sh[t * 4 + 2 * half + 1], sl[t * 4 + 2 * half + 1]);
                }
                if (half) l0_kb2(accL0, sh, sl, s >> 1, smc, lane);
            }
        }
        // ---- towerB half1: slots 14..17 (slot 17 merges meta cols 4..7, no lrelu) ----
        {
            float D[32];
            tower_half2<7, 1, 5, 4>(b + (size_t)rA0 * 102, b + (size_t)rA1 * 102,
                                    b + (size_t)rB0 * 102, b + (size_t)rB1 * 102,
                                    102, smc, TB_H, TB_L, JTB, lane, D);
#pragma unroll
            for (int nb = 0; nb < 3; nb++) {
                const int s = 14 + nb, half = s & 1;
#pragma unroll
                for (int t = 0; t < 2; t++) {
                    float d0 = lrelu(D[t * 16 + 4 * nb + 0]), d1 = lrelu(D[t * 16 + 4 * nb + 1]);
                    float d2 = lrelu(D[t * 16 + 4 * nb + 2]), d3 = lrelu(D[t * 16 + 4 * nb + 3]);
                    split_pack(d0, d1, sh[t * 4 + 2 * half + 0], sl[t * 4 + 2 * half + 0]);
                    split_pack(d2, d3, sh[t * 4 + 2 * half + 1], sl[t * 4 + 2 * half + 1]);
                }
                if (half) l0_kb2(accL0, sh, sl, s >> 1, smc, lane);
            }
            {   // s = 17 (odd): cols 0-3 = towerB outs 64-67 (lrelu), cols 4-7 = meta (raw)
                const int r0s[2] = { rA0, rB0 }, r1s[2] = { rA1, rB1 };
#pragma unroll
                for (int t = 0; t < 2; t++) {
                    float e0, e1, e2, e3;
                    if (t2 < 4) {
                        e0 = lrelu(D[t * 16 + 12 + 0]); e1 = lrelu(D[t * 16 + 12 + 1]);
                        e2 = lrelu(D[t * 16 + 12 + 2]); e3 = lrelu(D[t * 16 + 12 + 3]);
                    } else {
                        float2 u = *reinterpret_cast<const float2*>(meta + (size_t)r0s[t] * 4 + (t2 - 4));
                        float2 v = *reinterpret_cast<const float2*>(meta + (size_t)r1s[t] * 4 + (t2 - 4));
                        e0 = u.x; e1 = u.y; e2 = v.x; e3 = v.y;
                    }
                    split_pack(e0, e1, sh[t * 4 + 2], sl[t * 4 + 2]);
                    split_pack(e2, e3, sh[t * 4 + 3], sl[t * 4 + 3]);
                }
                l0_kb2(accL0, sh, sl, 8, smc, lane);
            }
        }

        // ---- L0 outputs -> fragments for L1 (per-tile stride 12) ----
        u32 h1[24], l1[24];
#pragma unroll
        for (int t = 0; t < 2; t++) {
#pragma unroll
            for (int nb = 0; nb < 5; nb++)
                toslot(accL0[t * 20 + 4 * nb + 0], accL0[t * 20 + 4 * nb + 1],
                       accL0[t * 20 + 4 * nb + 2], accL0[t * 20 + 4 * nb + 3],
                       h1 + t * 12, l1 + t * 12, nb, true);
            h1[t * 12 + 10] = 0; h1[t * 12 + 11] = 0;
            l1[t * 12 + 10] = 0; l1[t * 12 + 11] = 0;
        }

        {   // L1: K=48, N=40
            float D[40];
            layer2<3, 5>(h1, l1, smc, L1_H, L1_L, J1, lane, D);
#pragma unroll
            for (int t = 0; t < 2; t++) {
#pragma unroll
                for (int nb = 0; nb < 5; nb++)
                    toslot(D[t * 20 + 4 * nb + 0], D[t * 20 + 4 * nb + 1],
                           D[t * 20 + 4 * nb + 2], D[t * 20 + 4 * nb + 3],
                           h1 + t * 12, l1 + t * 12, nb, true);
                h1[t * 12 + 10] = 0; h1[t * 12 + 11] = 0;
                l1[t * 12 + 10] = 0; l1[t * 12 + 11] = 0;
            }
        }
        {   // L2: K=48, N=24
            float D[24];
            layer2<3, 3>(h1, l1, smc, L2_H, L2_L, J2, lane, D);
#pragma unroll
            for (int t = 0; t < 2; t++) {
#pragma unroll
                for (int nb = 0; nb < 3; nb++)
                    toslot(D[t * 12 + 4 * nb + 0], D[t * 12 + 4 * nb + 1],
                           D[t * 12 + 4 * nb + 2], D[t * 12 + 4 * nb + 3],
                           h1 + t * 12, l1 + t * 12, nb, true);
                h1[t * 12 + 6] = 0; h1[t * 12 + 7] = 0;
                l1[t * 12 + 6] = 0; l1[t * 12 + 7] = 0;
            }
        }
        const u32 lh[4] = { L3_H, L4_H, L5_H, L6_H };
        const u32 ll[4] = { L3_L, L4_L, L5_L, L6_L };
        const int lj[4] = { J3, J4, J5, J6 };
#pragma unroll
        for (int L = 0; L < 4; L++) {
            float D[24];
            layer2<2, 3>(h1, l1, smc, lh[L], ll[L], lj[L], lane, D);
#pragma unroll
            for (int t = 0; t < 2; t++) {
#pragma unroll
                for (int nb = 0; nb < 3; nb++)
                    toslot(D[t * 12 + 4 * nb + 0], D[t * 12 + 4 * nb + 1],
                           D[t * 12 + 4 * nb + 2], D[t * 12 + 4 * nb + 3],
                           h1 + t * 12, l1 + t * 12, nb, true);
                h1[t * 12 + 6] = 0; h1[t * 12 + 7] = 0;
                l1[t * 12 + 6] = 0; l1[t * 12 + 7] = 0;
            }
        }
        // L7: K=32, N=8
        float D7[8];
        layer2<2, 1>(h1, l1, smc, L7_H, L7_L, J7, lane, D7);

        // L8 (5->2) + L9 (2->1) scalar per tile; 4-lane butterfly per row group
        const float w8a0 = bs[JW8 + t2 * 2 + 0], w8b0 = bs[JW8 + t2 * 2 + 1];
        const float w8a1 = bs[JW8 + (t2 + 1) * 2 + 0], w8b1 = bs[JW8 + (t2 + 1) * 2 + 1];
        const float w90 = bs[JW9 + 0], w91 = bs[JW9 + 1], b9v = bs[JB9];
        const float b80 = bs[JB8 + 0], b81 = bs[JB8 + 1];
        const int r0s[2] = { rA0, rB0 }, r1s[2] = { rA1, rB1 };
#pragma unroll
        for (int t = 0; t < 2; t++) {
            float v0 = lrelu(D7[t * 4 + 0]), v1 = lrelu(D7[t * 4 + 1]);
            float v2 = lrelu(D7[t * 4 + 2]), v3 = lrelu(D7[t * 4 + 3]);
            float pa0 = fmaf(v0, w8a0, v1 * w8a1), pb0 = fmaf(v0, w8b0, v1 * w8b1);
            float pa1 = fmaf(v2, w8a0, v3 * w8a1), pb1 = fmaf(v2, w8b0, v3 * w8b1);
            pa0 += __shfl_xor_sync(0xFFFFFFFFu, pa0, 1); pa0 += __shfl_xor_sync(0xFFFFFFFFu, pa0, 2);
            pb0 += __shfl_xor_sync(0xFFFFFFFFu, pb0, 1); pb0 += __shfl_xor_sync(0xFFFFFFFFu, pb0, 2);
            pa1 += __shfl_xor_sync(0xFFFFFFFFu, pa1, 1); pa1 += __shfl_xor_sync(0xFFFFFFFFu, pa1, 2);
            pb1 += __shfl_xor_sync(0xFFFFFFFFu, pb1, 1); pb1 += __shfl_xor_sync(0xFFFFFFFFu, pb1, 2);
            float c8a = lrelu(pa0 + b80), c8b = lrelu(pb0 + b81);
            float o0 = lrelu(fmaf(c8a, w90, fmaf(c8b, w91, b9v)));
            c8a = lrelu(pa1 + b80); c8b = lrelu(pb1 + b81);
            float o1 = lrelu(fmaf(c8a, w90, fmaf(c8b, w91, b9v)));
            if ((lane & 3) == 0) { outp[r0s[t]] = o0; outp[r1s[t]] = o1; }
        }
    }
}

extern "C" void kernel_launch(void* const* d_in, const int* in_sizes, int n_in,
                              void* d_out, int out_size) {
    const float* a    = (const float*)d_in[0];
    const float* b    = (const float*)d_in[1];
    const float* meta = (const float*)d_in[2];
    const float* Wa   = (const float*)d_in[3];
    const float* ba   = (const float*)d_in[4];
    const float* Wb   = (const float*)d_in[5];
    const float* bb   = (const float*)d_in[6];
    const float* W[10], *Bb[10];
    for (int i = 0; i < 10; i++) {
        W[i]  = (const float*)d_in[7 + 2 * i];
        Bb[i] = (const float*)d_in[8 + 2 * i];
    }
    float* outp = (float*)d_out;
    const int nrows = in_sizes[0] / 45;
    const int npairs = nrows / 32;   // 8192 pairs of 16-row tiles

    cudaFuncSetAttribute(Net_67954972557347_kernel,
                         cudaFuncAttributeMaxDynamicSharedMemorySize, SMEM_TOTAL);

    reset_ctr_kernel<<<1, 1>>>();
    // 96.5 KB smem, 1 CTA/SM x 384 threads = 12 warps; 2 tiles (32 rows) per warp:
    // every weight LDS feeds 6 MMAs (was 3) -> L1 weight bytes halved; 2x MMA ILP.
    Net_67954972557347_kernel<<<148, 384, SMEM_TOTAL>>>(
        a, b, meta, Wa, ba, Wb, bb,
        W[0], Bb[0], W[1], Bb[1], W[2], Bb[2], W[3], Bb[3], W[4], Bb[4],
        W[5], Bb[5], W[6], Bb[6], W[7], Bb[7], W[8], Bb[8], W[9], Bb[9],
        outp, npairs);
}